// round 12
// baseline (speedup 1.0000x reference)
#include <cuda_runtime.h>
#include <cstdint>

// Problem constants
#define BATCH   1024
#define IN_H    128
#define IN_W    128
#define WPAD    132
#define NKW     25
#define NK      625
#define KHW     100

// Tiling
#define IGROUPS 5            // blockIdx.y
#define KL      125          // outputs per block
#define XROWS   30           // staged padded rows per group
#define XSQ     548          // words per row: 132 cols * 4 imgs + pad
                             //   (5*XSQ/4 mod 8 == 5 -> LDS.128 phases stay conflict-free
                             //    across il boundaries; within il, 5jj mod 8 covers all 8)
#define BUFQ    (XROWS*XSQ)  // 16440 words per buffer (4 images)
#define HB      4            // images per group (packed per float4)
#define DEPTH   3            // ring buffers, fills 2 ahead
#define BSPLIT  29           // 29*5 = 145 blocks, 1 per SM
#define NT      256
#define SMEM_BYTES (DEPTH*BUFQ*4)   // 197,280 B

// Extracted weights: g_w[k*100 + dy*10 + dx]
__device__ float g_w[NK * KHW];

__global__ void extract_kernel(const float* __restrict__ W)
{
    int idx = blockIdx.x * blockDim.x + threadIdx.x;
    if (idx >= NK * KHW) return;
    int k  = idx / KHW;
    int d  = idx - k * KHW;
    int dy = d / 10;
    int dx = d - dy * 10;
    int ki = k / NKW;
    int kj = k - ki * NKW;
    int r  = (ki * 5 + dy) * WPAD + (kj * 5 + dx);
    g_w[idx] = W[(size_t)r * NK + k];
}

// ---------------------------------------------------------------------------
// Image-quad layout: word(rr, cc, img) = rr*XSQ + cc*4 + img (cc = padded col,
// real col c at cc=c+2). One LDS.128 = same pixel of 4 images -> 4 independent
// FMA chains per weight, 4x fewer LDS.
// Fill (all 8 warps, plain LDG.32 -> STS.32): lane l takes img = l&3,
// col = cb*8 + (l>>2); dst word = base + r*XSQ + 8 + 32*cb + l  ==> 32
// consecutive words per STS (conflict-free), 4x32B coalesced LDG sectors.
// Loads batched 10-deep in regs. Ring of 3 buffers, fills 2 groups ahead,
// ordered by ONE __syncthreads per iteration (no async machinery).
// ---------------------------------------------------------------------------
__global__ __launch_bounds__(NT, 1)
void lc2d_kernel(const float* __restrict__ x,
                 const float* __restrict__ bias,
                 float* __restrict__ out)
{
    extern __shared__ float xs[];

    const int bx   = blockIdx.x;   // 0..28
    const int ig   = blockIdx.y;   // 0..4
    const int tid  = threadIdx.x;  // 0..255
    const int wid  = tid >> 5;
    const int lane = tid & 31;

    // zero halo pixel-quads once: padded cols 0,1,130,131 of every row/buffer
    for (int idx = tid; idx < DEPTH * XROWS * 4; idx += NT) {
        int b  = idx >> 2;
        int hc = idx & 3;
        int cc = (hc < 2) ? hc : 128 + hc;   // 0,1,130,131
        float4* p = reinterpret_cast<float4*>(&xs[b * XSQ + cc * 4]);
        *p = make_float4(0.f, 0.f, 0.f, 0.f);
    }

    const int  kl = (tid < KL) ? tid : KL - 1;
    const bool tv = (tid < KL);          // compute validity (warps 0-3 only hold <125)
    const int  il = kl / 25;
    const int  jj = kl - il * 25;

    // ---- 100 weights into registers (used by warps 0-3) ----
    float4 w4[25];
    float  bv = 0.f;
    if (wid < 4) {
        const float4* wg = reinterpret_cast<const float4*>(g_w) + (ig * KL + kl) * 25;
        #pragma unroll
        for (int j = 0; j < 25; ++j) w4[j] = __ldg(&wg[j]);
        bv = __ldg(&bias[ig * KL + kl]);
    }

    const int r0       = ig * 25 - 2;
    const int nb_total = (BATCH - 1 - bx) / BSPLIT + 1;   // 35 or 36
    const int NG       = (nb_total + HB - 1) / HB;        // 9

    // fill lane roles
    const int  f_img  = lane & 3;
    const int  f_c    = lane >> 2;        // 0..7
    // group-invariant source base (image index varies with hg)
    // fill buffer (hg % DEPTH) with group hg
    auto fill = [&](int hg) {
        int  buf  = hg % DEPTH;
        int  t    = hg * HB + f_img;
        bool tval = t < nb_total;
        const float* img_base =
            x + (size_t)(bx + t * BSPLIT) * (IN_H * IN_W) + f_c;
        float* dst_base = xs + buf * BUFQ + 8 + lane;
        // 60 tasks per warp, batched 10 LDG then 10 STS
        #pragma unroll
        for (int c = 0; c < 6; ++c) {
            float v[10];
            #pragma unroll
            for (int j = 0; j < 10; ++j) {
                int tau = wid * 60 + c * 10 + j;
                int r   = tau >> 4;
                int cb  = tau & 15;
                int rr  = r0 + r;
                bool ok = tval & (rr >= 0) & (rr < IN_H);
                v[j] = ok ? __ldg(img_base + rr * IN_W + cb * 8) : 0.f;
            }
            #pragma unroll
            for (int j = 0; j < 10; ++j) {
                int tau = wid * 60 + c * 10 + j;
                int r   = tau >> 4;
                int cb  = tau & 15;
                dst_base[r * XSQ + 32 * cb] = v[j];
            }
        }
    };

    fill(0);
    fill(1);
    __syncthreads();

    const int xoff = il * 5 * XSQ + jj * 20;   // quad-aligned word offset

    for (int g = 0; g < NG; ++g) {
        // compute on buffer g%DEPTH (filled 2 iterations ago / prologue)
        if (wid < 4) {
            const float* xp = xs + (g % DEPTH) * BUFQ + xoff;
            float4 acc0 = make_float4(0.f, 0.f, 0.f, 0.f);
            float4 acc1 = make_float4(0.f, 0.f, 0.f, 0.f);
            const float* wf = reinterpret_cast<const float*>(w4);
            #pragma unroll
            for (int dy = 0; dy < 10; ++dy) {
                const float* row = xp + dy * XSQ;
                const float* wr  = wf + dy * 10;
                #pragma unroll
                for (int dx = 0; dx < 10; dx += 2) {
                    float4 v0 = *reinterpret_cast<const float4*>(row + dx * 4);
                    float4 v1 = *reinterpret_cast<const float4*>(row + dx * 4 + 4);
                    float w0 = wr[dx], w1 = wr[dx + 1];
                    acc0.x = fmaf(v0.x, w0, acc0.x);
                    acc0.y = fmaf(v0.y, w0, acc0.y);
                    acc0.z = fmaf(v0.z, w0, acc0.z);
                    acc0.w = fmaf(v0.w, w0, acc0.w);
                    acc1.x = fmaf(v1.x, w1, acc1.x);
                    acc1.y = fmaf(v1.y, w1, acc1.y);
                    acc1.z = fmaf(v1.z, w1, acc1.z);
                    acc1.w = fmaf(v1.w, w1, acc1.w);
                }
            }
            if (tv) {
                float r4[4] = { acc0.x + acc1.x + bv, acc0.y + acc1.y + bv,
                                acc0.z + acc1.z + bv, acc0.w + acc1.w + bv };
                int tA = g * HB;
                int ob = ig * KL + kl;
                #pragma unroll
                for (int i = 0; i < 4; ++i)
                    if (tA + i < nb_total)
                        out[(size_t)(bx + (tA + i) * BSPLIT) * NK + ob] = r4[i];
            }
        }

        // then fill group g+2 into buffer (g+2)%DEPTH == (g-1)%DEPTH,
        // whose consumer finished before the barrier ending iteration g-1.
        if (g + 2 < NG) fill(g + 2);

        __syncthreads();
    }
}

// ---------------------------------------------------------------------------
extern "C" void kernel_launch(void* const* d_in, const int* in_sizes, int n_in,
                              void* d_out, int out_size)
{
    const float* x    = (const float*)d_in[0];   // [1024,128,128]
    const float* W    = (const float*)d_in[1];   // [17424,625]
    const float* bias = (const float*)d_in[2];   // [25,25]
    float* out = (float*)d_out;                  // [1024,25,25]

    cudaFuncSetAttribute(lc2d_kernel,
                         cudaFuncAttributeMaxDynamicSharedMemorySize, SMEM_BYTES);

    extract_kernel<<<(NK * KHW + 255) / 256, 256>>>(W);

    dim3 grid(BSPLIT, IGROUPS);
    lc2d_kernel<<<grid, NT, SMEM_BYTES>>>(x, bias, out);
}

// round 13
// speedup vs baseline: 2.9454x; 2.9454x over previous
#include <cuda_runtime.h>
#include <cstdint>

// Problem constants
#define BATCH   1024
#define IN_H    128
#define IN_W    128
#define WPAD    132
#define NKW     25
#define NK      625
#define KHW     100

// Tiling
#define IGROUPS 5           // blockIdx.y: groups of 5 output rows
#define KL      125         // outputs per block (5 rows * 25 cols)
#define XROWS   30          // padded input rows per 5 output rows
#define XS      152         // x smem row stride: 152 mod 32 = 24 -> exactly ONE
                            //   il-boundary bank-conflict pair (optimal among mult-of-4)
#define IMGW    (XROWS*XS)  // 4560 words per image tile
#define HB      3           // images per buffer (3 images x 2 accumulators = 6 chains)
#define BUFW    (HB*IMGW)   // 13680 words
#define DEPTH   2           // double buffer
#define BSPLIT  58          // batch stripes: 58*5 = 290 blocks = 2 per SM
#define NT      128
#define SMEM_BYTES (DEPTH*BUFW*4)   // 109,440 B/block (x2 = 218.9 KB/SM)

// Extracted weights: g_w[k*100 + dy*10 + dx]
__device__ float g_w[NK * KHW];

__global__ void extract_kernel(const float* __restrict__ W)
{
    int idx = blockIdx.x * blockDim.x + threadIdx.x;
    if (idx >= NK * KHW) return;
    int k  = idx / KHW;
    int d  = idx - k * KHW;
    int dy = d / 10;
    int dx = d - dy * 10;
    int ki = k / NKW;
    int kj = k - ki * NKW;
    int r  = (ki * 5 + dy) * WPAD + (kj * 5 + dx);
    g_w[idx] = W[(size_t)r * NK + k];
}

__device__ __forceinline__ void cp16(unsigned int dst_smem, const float* src, int src_sz)
{
    asm volatile("cp.async.cg.shared.global [%0], [%1], 16, %2;\n"
                 :: "r"(dst_smem), "l"(src), "r"(src_sz));
}

// ---------------------------------------------------------------------------
// 128 threads, 2 blocks/SM. Thread kl (<125) holds its output's 100 weights
// in registers, computes 3 images per group with SIX independent accumulator
// chains (even/odd dx per image) so the LDS->FMA and FMA->FMA dependency
// depth is halved vs R9. Double-buffered cp.async fill (16B, coalesced).
// ---------------------------------------------------------------------------
__global__ __launch_bounds__(NT, 2)
void lc2d_kernel(const float* __restrict__ x,
                 const float* __restrict__ bias,
                 float* __restrict__ out)
{
    extern __shared__ float xs[];
    const unsigned int xs_base = (unsigned int)__cvta_generic_to_shared(xs);

    const int bx  = blockIdx.x;   // 0..57
    const int ig  = blockIdx.y;   // 0..4
    const int tid = threadIdx.x;  // 0..127

    // zero halo columns once (padded cols -2,-1,130,131 of every staged row)
    for (int idx = tid; idx < DEPTH * HB * XROWS; idx += NT) {
        float* p = &xs[idx * XS];
        p[2] = 0.f; p[3] = 0.f; p[132] = 0.f; p[133] = 0.f;
    }

    const int kl  = tid < KL ? tid : KL - 1;
    const bool tv = tid < KL;
    const int il  = kl / 25;
    const int jj  = kl - il * 25;

    // ---- 100 weights into registers ----
    float4 w4[25];
    {
        const float4* wg = reinterpret_cast<const float4*>(g_w) + (ig * KL + kl) * 25;
        #pragma unroll
        for (int j = 0; j < 25; ++j) w4[j] = __ldg(&wg[j]);
    }
    const float bv = __ldg(&bias[ig * KL + kl]);

    const int r0       = ig * 25 - 2;
    const int nb_total = (BATCH - 1 - bx) / BSPLIT + 1;   // 17 or 18
    const int NG       = (nb_total + HB - 1) / HB;        // 6

    const int xoff = (il * 5) * XS + jj * 5 + 2;

    // fill buffer (hg & 1) with group hg (3 images): 2880 float4
    auto fill = [&](int hg) {
        int buf = hg & 1;
        #pragma unroll
        for (int i = 0; i < 23; ++i) {
            int idx = tid + i * NT;
            if (idx < HB * XROWS * 32) {
                int bl  = idx / (XROWS * 32);
                int rem = idx - bl * (XROWS * 32);
                int rr  = rem >> 5;
                int c4  = rem & 31;
                int t   = hg * HB + bl;
                int r   = r0 + rr;
                bool v  = (t < nb_total) & (r >= 0) & (r < IN_H);
                const float* src = v
                    ? x + (size_t)(bx + t * BSPLIT) * (IN_H * IN_W) + r * IN_W + c4 * 4
                    : x;
                unsigned int dst = xs_base +
                    (unsigned int)(buf * BUFW + bl * IMGW + rr * XS + 4 + c4 * 4) * 4u;
                cp16(dst, src, v ? 16 : 0);
            }
        }
        asm volatile("cp.async.commit_group;\n");
    };

    fill(0);
    fill(1);

    for (int g = 0; g < NG; ++g) {
        if (g + 1 < NG) asm volatile("cp.async.wait_group 1;\n");
        else            asm volatile("cp.async.wait_group 0;\n");
        __syncthreads();

        const int buf = g & 1;
        {
            const float* xpA = xs + buf * BUFW + xoff;
            const float* xpB = xpA + IMGW;
            const float* xpC = xpB + IMGW;
            // six independent chains: {image A,B,C} x {even,odd dx}
            float a0e = 0.f, a0o = 0.f;
            float a1e = 0.f, a1o = 0.f;
            float a2e = 0.f, a2o = 0.f;
            const float* wf = reinterpret_cast<const float*>(w4);
            #pragma unroll
            for (int dy = 0; dy < 10; ++dy) {
                const float* rA = xpA + dy * XS;
                const float* rB = xpB + dy * XS;
                const float* rC = xpC + dy * XS;
                const float* wr = wf + dy * 10;
                #pragma unroll
                for (int dx = 0; dx < 10; dx += 2) {
                    float w0 = wr[dx], w1 = wr[dx + 1];
                    a0e = fmaf(rA[dx    ], w0, a0e);
                    a1e = fmaf(rB[dx    ], w0, a1e);
                    a2e = fmaf(rC[dx    ], w0, a2e);
                    a0o = fmaf(rA[dx + 1], w1, a0o);
                    a1o = fmaf(rB[dx + 1], w1, a1o);
                    a2o = fmaf(rC[dx + 1], w1, a2o);
                }
            }
            int tA = g * HB;
            int ob = ig * KL + kl;
            if (tv) {
                if (tA < nb_total)
                    out[(size_t)(bx + tA * BSPLIT) * NK + ob] = a0e + a0o + bv;
                if (tA + 1 < nb_total)
                    out[(size_t)(bx + (tA + 1) * BSPLIT) * NK + ob] = a1e + a1o + bv;
                if (tA + 2 < nb_total)
                    out[(size_t)(bx + (tA + 2) * BSPLIT) * NK + ob] = a2e + a2o + bv;
            }
        }
        __syncthreads();

        if (g + 2 < NG) fill(g + 2);
    }
}

// ---------------------------------------------------------------------------
extern "C" void kernel_launch(void* const* d_in, const int* in_sizes, int n_in,
                              void* d_out, int out_size)
{
    const float* x    = (const float*)d_in[0];   // [1024,128,128]
    const float* W    = (const float*)d_in[1];   // [17424,625]
    const float* bias = (const float*)d_in[2];   // [25,25]
    float* out = (float*)d_out;                  // [1024,25,25]

    cudaFuncSetAttribute(lc2d_kernel,
                         cudaFuncAttributeMaxDynamicSharedMemorySize, SMEM_BYTES);

    extract_kernel<<<(NK * KHW + 255) / 256, 256>>>(W);

    dim3 grid(BSPLIT, IGROUPS);
    lc2d_kernel<<<grid, NT, SMEM_BYTES>>>(x, bias, out);
}